// round 4
// baseline (speedup 1.0000x reference)
#include <cuda_runtime.h>
#include <math.h>

// InfoNCE loss, fully fused. B=16384, D=256, T=0.07.
//   1. normalize q (scaled 1/T) -> g_qn, d -> g_dn
//   2. diag[i] = qn_i . dn_i
//   3. tiled 128x128 GEMM (f32x2 packed FFMA) + per-tile exp-sum partials
//      with fixed shift M = 1/T >= any sim  -> stable, no running max, no atomics
//   4. deterministic reduction -> scalar loss
// sim (1 GB) never materialized.

#define B_N 16384
#define D_K 256
#define NT  128
#define TM  128
#define KC  16
#define M_SHIFT 14.285714285714286f   // 1/0.07

typedef unsigned long long u64;

static __device__ float g_qn[B_N * D_K];
static __device__ float g_dn[B_N * D_K];
static __device__ float g_diag[B_N];
static __device__ float g_rowpart[NT * B_N];   // [colTile][row]
static __device__ float g_colpart[NT * B_N];   // [rowTile][col]
static __device__ float g_blockRow[64];
static __device__ float g_blockCol[64];

// ---- packed f32x2 helpers (FFMA2 path; ptxas won't emit it from C++) ------
__device__ __forceinline__ u64 dup2(float x) {
    u64 r; asm("mov.b64 %0, {%1, %1};" : "=l"(r) : "f"(x)); return r;
}
__device__ __forceinline__ void fma2(u64& d, u64 a, u64 b) {
    asm("fma.rn.f32x2 %0, %1, %2, %3;" : "=l"(d) : "l"(a), "l"(b), "l"(d));
}
__device__ __forceinline__ void unpack2(u64 v, float& lo, float& hi) {
    asm("mov.b64 {%0, %1}, %2;" : "=f"(lo), "=f"(hi) : "l"(v));
}

// ---------------------------------------------------------------------------
// 1. Normalize: one warp per row. out = in / max(||in||, eps) * extra_scale
// ---------------------------------------------------------------------------
__global__ void normalize_kernel(const float* __restrict__ in, int is_q) {
    int warp = threadIdx.x >> 5;
    int lane = threadIdx.x & 31;
    int row  = blockIdx.x * 8 + warp;
    const float* src = in + (size_t)row * D_K;
    float v[8];
    float s = 0.f;
#pragma unroll
    for (int j = 0; j < 8; ++j) {
        v[j] = src[j * 32 + lane];
        s += v[j] * v[j];
    }
#pragma unroll
    for (int o = 16; o > 0; o >>= 1) s += __shfl_xor_sync(0xffffffffu, s, o);
    float extra = is_q ? (1.0f / 0.07f) : 1.0f;
    float scale = extra / fmaxf(sqrtf(s), 1e-12f);
    float* dst = (is_q ? g_qn : g_dn) + (size_t)row * D_K;
#pragma unroll
    for (int j = 0; j < 8; ++j) dst[j * 32 + lane] = v[j] * scale;
}

// ---------------------------------------------------------------------------
// 2. diag[i] = qn_i . dn_i  (one warp per row)
// ---------------------------------------------------------------------------
__global__ void diag_kernel() {
    int warp = threadIdx.x >> 5;
    int lane = threadIdx.x & 31;
    int row  = blockIdx.x * 8 + warp;
    const float* a = g_qn + (size_t)row * D_K;
    const float* b = g_dn + (size_t)row * D_K;
    float s = 0.f;
#pragma unroll
    for (int j = 0; j < 8; ++j) {
        int c = j * 32 + lane;
        s += a[c] * b[c];
    }
#pragma unroll
    for (int o = 16; o > 0; o >>= 1) s += __shfl_xor_sync(0xffffffffu, s, o);
    if (lane == 0) g_diag[row] = s;
}

// ---------------------------------------------------------------------------
// 3. Fused GEMM + partial-exp-sum. Grid (NT, NT), block 256 (16x16 threads),
//    thread micro-tile 8x8, accumulated as 4 row-pairs x 8 cols in f32x2.
// ---------------------------------------------------------------------------
__global__ __launch_bounds__(256) void gemm_lse_kernel() {
    __shared__ float As[KC][TM];   // [k][row]
    __shared__ float Bs[KC][TM];   // [k][col]
    __shared__ float red[TM * 16];

    int tid = threadIdx.x;
    int tx = tid & 15;          // col group
    int ty = tid >> 4;          // row group
    int rowBase = blockIdx.y * TM;
    int colBase = blockIdx.x * TM;

    // acc2[ip][j]: lo = row 2*ip, hi = row 2*ip+1, column j
    u64 acc2[4][8];
#pragma unroll
    for (int ip = 0; ip < 4; ++ip)
#pragma unroll
        for (int j = 0; j < 8; ++j) acc2[ip][j] = 0ull;

    for (int kc = 0; kc < D_K; kc += KC) {
        // Load 128 rows x 16 k of A and B, transposed into [k][row]
#pragma unroll
        for (int it = 0; it < 2; ++it) {
            int e  = tid + it * 256;
            int r  = e >> 2;
            int c4 = (e & 3) * 4;
            float4 va = *(const float4*)&g_qn[(size_t)(rowBase + r) * D_K + kc + c4];
            As[c4 + 0][r] = va.x; As[c4 + 1][r] = va.y;
            As[c4 + 2][r] = va.z; As[c4 + 3][r] = va.w;
            float4 vb = *(const float4*)&g_dn[(size_t)(colBase + r) * D_K + kc + c4];
            Bs[c4 + 0][r] = vb.x; Bs[c4 + 1][r] = vb.y;
            Bs[c4 + 2][r] = vb.z; Bs[c4 + 3][r] = vb.w;
        }
        __syncthreads();
#pragma unroll
        for (int k = 0; k < KC; ++k) {
            // A row-pairs load directly as 64-bit words (rows 2ip, 2ip+1)
            const u64* ap64 = (const u64*)&As[k][ty * 8];
            u64 ap[4];
#pragma unroll
            for (int ip = 0; ip < 4; ++ip) ap[ip] = ap64[ip];
            // B lanes duplicated into both halves
            float4 b0 = *(const float4*)&Bs[k][tx * 8];
            float4 b1 = *(const float4*)&Bs[k][tx * 8 + 4];
            u64 bp[8];
            bp[0] = dup2(b0.x); bp[1] = dup2(b0.y);
            bp[2] = dup2(b0.z); bp[3] = dup2(b0.w);
            bp[4] = dup2(b1.x); bp[5] = dup2(b1.y);
            bp[6] = dup2(b1.z); bp[7] = dup2(b1.w);
#pragma unroll
            for (int ip = 0; ip < 4; ++ip)
#pragma unroll
                for (int j = 0; j < 8; ++j) fma2(acc2[ip][j], ap[ip], bp[j]);
        }
        __syncthreads();
    }

    // Epilogue: e = exp(sim - M); per-row and per-col partial sums.
    float rowp[8], colp[8];
#pragma unroll
    for (int i = 0; i < 8; ++i) rowp[i] = 0.f;
#pragma unroll
    for (int j = 0; j < 8; ++j) colp[j] = 0.f;
#pragma unroll
    for (int ip = 0; ip < 4; ++ip)
#pragma unroll
        for (int j = 0; j < 8; ++j) {
            float lo, hi;
            unpack2(acc2[ip][j], lo, hi);
            float e0 = __expf(lo - M_SHIFT);
            float e1 = __expf(hi - M_SHIFT);
            rowp[2 * ip]     += e0;
            rowp[2 * ip + 1] += e1;
            colp[j] += e0 + e1;
        }

    // Deterministic cross-thread reduce over the 16 col-groups (rows)
#pragma unroll
    for (int i = 0; i < 8; ++i) red[(ty * 8 + i) * 16 + tx] = rowp[i];
    __syncthreads();
    if (tid < TM) {
        float s = 0.f;
#pragma unroll
        for (int t = 0; t < 16; ++t) s += red[tid * 16 + t];
        g_rowpart[(size_t)blockIdx.x * B_N + rowBase + tid] = s;
    }
    __syncthreads();
    // cols
#pragma unroll
    for (int j = 0; j < 8; ++j) red[(tx * 8 + j) * 16 + ty] = colp[j];
    __syncthreads();
    if (tid < TM) {
        float s = 0.f;
#pragma unroll
        for (int t = 0; t < 16; ++t) s += red[tid * 16 + t];
        g_colpart[(size_t)blockIdx.y * B_N + colBase + tid] = s;
    }
}

// ---------------------------------------------------------------------------
// 4a. Per-row loss terms + per-block deterministic tree reduce
// ---------------------------------------------------------------------------
__global__ void finalize1_kernel() {
    int i = blockIdx.x * 256 + threadIdx.x;
    float rs = 0.f, cs = 0.f;
#pragma unroll 4
    for (int t = 0; t < NT; ++t) {
        rs += g_rowpart[(size_t)t * B_N + i];
        cs += g_colpart[(size_t)t * B_N + i];
    }
    float dg = g_diag[i];
    float rw = M_SHIFT + logf(rs) - dg;
    float cw = M_SHIFT + logf(cs) - dg;

    __shared__ float sr[256], sc[256];
    sr[threadIdx.x] = rw;
    sc[threadIdx.x] = cw;
    __syncthreads();
    for (int o = 128; o > 0; o >>= 1) {
        if (threadIdx.x < o) {
            sr[threadIdx.x] += sr[threadIdx.x + o];
            sc[threadIdx.x] += sc[threadIdx.x + o];
        }
        __syncthreads();
    }
    if (threadIdx.x == 0) {
        g_blockRow[blockIdx.x] = sr[0];
        g_blockCol[blockIdx.x] = sc[0];
    }
}

// 4b. Final scalar
__global__ void finalize2_kernel(float* out) {
    float sR = 0.f, sC = 0.f;
    for (int b = 0; b < 64; ++b) {
        sR += g_blockRow[b];
        sC += g_blockCol[b];
    }
    out[0] = (sR + sC) / (2.0f * (float)B_N);
}

// ---------------------------------------------------------------------------
extern "C" void kernel_launch(void* const* d_in, const int* in_sizes, int n_in,
                              void* d_out, int out_size) {
    const float* q = (const float*)d_in[0];
    const float* d = (const float*)d_in[1];
    float* out = (float*)d_out;

    normalize_kernel<<<B_N / 8, 256>>>(q, 1);
    normalize_kernel<<<B_N / 8, 256>>>(d, 0);
    diag_kernel<<<B_N / 8, 256>>>();
    dim3 grid(NT, NT);
    gemm_lse_kernel<<<grid, 256>>>();
    finalize1_kernel<<<B_N / 256, 256>>>();
    finalize2_kernel<<<1, 1>>>(out);
}

// round 9
// speedup vs baseline: 6.9565x; 6.9565x over previous
#include <cuda_runtime.h>
#include <cuda_bf16.h>
#include <math.h>
#include <cstdint>

// InfoNCE loss. B=16384, D=256, T=0.07. mma.sync (bf16 HMMA) path —
// tcgen05 is unavailable because the harness compiles via compute_103 PTX.
//   1. normalize q (scaled 1/T) -> g_qb (bf16), d -> g_db (bf16)
//   2. diag[i] = qb_i . db_i (fp32)
//   3. per 128x128 tile: cp.async double-buffered bf16 MMA, epilogue
//      exp(sim - M), M = 1/T >= max sim -> stable, no atomics, deterministic
//   4. deterministic reduce -> scalar. sim (1 GB) never materialized.

#define B_N 16384
#define D_K 256
#define NT  128
#define M_SHIFT 14.285714285714286f   // 1/0.07

static __device__ __nv_bfloat16 g_qb[B_N * D_K];
static __device__ __nv_bfloat16 g_db[B_N * D_K];
static __device__ float g_diag[B_N];
static __device__ float g_rowpart[NT * B_N];   // [colTile][row]
static __device__ float g_colpart[NT * B_N];   // [rowTile][col]
static __device__ float g_blockRow[64];
static __device__ float g_blockCol[64];

// ---------------- PTX helpers (all valid on plain sm_103 target) -----------
__device__ __forceinline__ uint32_t smem_u32(const void* p) {
    uint32_t a;
    asm("{ .reg .u64 t; cvta.to.shared.u64 t, %1; cvt.u32.u64 %0, t; }" : "=r"(a) : "l"(p));
    return a;
}
__device__ __forceinline__ void cp16(uint32_t dst, const void* src) {
    asm volatile("cp.async.cg.shared.global [%0], [%1], 16;" :: "r"(dst), "l"(src) : "memory");
}
#define CP_COMMIT() asm volatile("cp.async.commit_group;" ::: "memory")
#define CP_WAIT(n)  asm volatile("cp.async.wait_group %0;" :: "n"(n) : "memory")

#define LDSM4(r0, r1, r2, r3, addr)                                          \
    asm volatile("ldmatrix.sync.aligned.m8n8.x4.shared.b16 {%0,%1,%2,%3}, [%4];" \
        : "=r"(r0), "=r"(r1), "=r"(r2), "=r"(r3) : "r"(addr))

#define MMA16816(c, a, b)                                                    \
    asm volatile("mma.sync.aligned.m16n8k16.row.col.f32.bf16.bf16.f32 "      \
        "{%0,%1,%2,%3}, {%4,%5,%6,%7}, {%8,%9}, {%0,%1,%2,%3};"              \
        : "+f"((c)[0]), "+f"((c)[1]), "+f"((c)[2]), "+f"((c)[3])             \
        : "r"((a)[0]), "r"((a)[1]), "r"((a)[2]), "r"((a)[3]),                \
          "r"((b)[0]), "r"((b)[1]))

// ---------------------------------------------------------------------------
// 1. Normalize -> bf16 (q scaled by 1/T). One warp per row.
// ---------------------------------------------------------------------------
__global__ void normalize_kernel(const float* __restrict__ in, int is_q) {
    int warp = threadIdx.x >> 5;
    int lane = threadIdx.x & 31;
    int row  = blockIdx.x * 8 + warp;
    const float* src = in + (size_t)row * D_K;
    float v[8];
    float s = 0.f;
#pragma unroll
    for (int j = 0; j < 8; ++j) { v[j] = src[j * 32 + lane]; s += v[j] * v[j]; }
#pragma unroll
    for (int o = 16; o > 0; o >>= 1) s += __shfl_xor_sync(0xffffffffu, s, o);
    float extra = is_q ? (1.0f / 0.07f) : 1.0f;
    float scale = extra / fmaxf(sqrtf(s), 1e-12f);
    __nv_bfloat16* dst = (is_q ? g_qb : g_db) + (size_t)row * D_K;
#pragma unroll
    for (int j = 0; j < 8; ++j) dst[j * 32 + lane] = __float2bfloat16(v[j] * scale);
}

// ---------------------------------------------------------------------------
// 2. diag[i] = qb_i . db_i  (fp32 accumulate; matches bf16 GEMM inputs)
// ---------------------------------------------------------------------------
__global__ void diag_kernel() {
    int warp = threadIdx.x >> 5;
    int lane = threadIdx.x & 31;
    int row  = blockIdx.x * 8 + warp;
    const __nv_bfloat16* a = g_qb + (size_t)row * D_K;
    const __nv_bfloat16* b = g_db + (size_t)row * D_K;
    float s = 0.f;
#pragma unroll
    for (int j = 0; j < 8; ++j) {
        int c = j * 32 + lane;
        s += __bfloat162float(a[c]) * __bfloat162float(b[c]);
    }
#pragma unroll
    for (int o = 16; o > 0; o >>= 1) s += __shfl_xor_sync(0xffffffffu, s, o);
    if (lane == 0) g_diag[row] = s;
}

// ---------------------------------------------------------------------------
// 3. MMA GEMM + exp partials. Grid (NT, NT), 256 threads (8 warps, 2x4).
//    SMEM: stage0 A[32K] B[32K], stage1 A[32K] B[32K], rowred 2K, colred 1K.
//    Smem tile layout: [row][16B chunk c], swizzled c' = c ^ (row & 7).
// ---------------------------------------------------------------------------
#define SMEM_ROWRED 131072
#define SMEM_COLRED 133120
#define SMEM_SZ     134144

__global__ __launch_bounds__(256, 1) void gemm_lse_kernel() {
    extern __shared__ char smem[];
    uint32_t sb = smem_u32(smem);
    int tid = threadIdx.x;
    int lane = tid & 31;
    int wid  = tid >> 5;
    int wr = wid >> 2;         // warp row (0..1) -> 64 rows
    int wc = wid & 3;          // warp col (0..3) -> 32 cols
    int rowBase = blockIdx.y * 128;
    int colBase = blockIdx.x * 128;

    // ---- issue both K-stages of cp.async loads (A=q rows, B=d rows) ----
#pragma unroll
    for (int s = 0; s < 2; ++s) {
#pragma unroll
        for (int it = 0; it < 8; ++it) {
            int e = it * 256 + tid;          // 0..2047
            int r = e >> 4, c = e & 15;      // row, 16B chunk within 128-k chunk
            uint32_t dst = sb + s * 65536 + r * 256 + ((c ^ (r & 7)) << 4);
            cp16(dst,         (const char*)(g_qb + (size_t)(rowBase + r) * D_K) + s * 256 + c * 16);
            cp16(dst + 32768, (const char*)(g_db + (size_t)(colBase + r) * D_K) + s * 256 + c * 16);
        }
        CP_COMMIT();
    }

    float acc[4][4][4];
#pragma unroll
    for (int mt = 0; mt < 4; ++mt)
#pragma unroll
        for (int nt = 0; nt < 4; ++nt)
#pragma unroll
            for (int k = 0; k < 4; ++k) acc[mt][nt][k] = 0.f;

    // per-lane ldmatrix row/chunk components
    int aRowL   = wr * 64 + (lane & 15);            // + mt*16
    int aChunkL = lane >> 4;                        // + 2*ks
    int bRowL   = wc * 32 + ((lane >> 4) & 1) * 8 + (lane & 7);  // + p*16
    int bChunkL = (lane >> 3) & 1;                  // + 2*ks

#pragma unroll
    for (int s = 0; s < 2; ++s) {
        if (s == 0) { CP_WAIT(1); } else { CP_WAIT(0); }
        __syncthreads();
        uint32_t aBase = sb + s * 65536;
        uint32_t bBase = aBase + 32768;
#pragma unroll
        for (int ks = 0; ks < 8; ++ks) {
            uint32_t a[4][4];
#pragma unroll
            for (int mt = 0; mt < 4; ++mt) {
                int rrow = aRowL + mt * 16;
                int cc = 2 * ks + aChunkL;
                uint32_t ad = aBase + rrow * 256 + (((cc) ^ (rrow & 7)) << 4);
                LDSM4(a[mt][0], a[mt][1], a[mt][2], a[mt][3], ad);
            }
            uint32_t b[4][2];
#pragma unroll
            for (int p = 0; p < 2; ++p) {
                int rrow = bRowL + p * 16;
                int cc = 2 * ks + bChunkL;
                uint32_t bd = bBase + rrow * 256 + (((cc) ^ (rrow & 7)) << 4);
                uint32_t r0, r1, r2, r3;
                LDSM4(r0, r1, r2, r3, bd);
                b[2 * p][0] = r0; b[2 * p][1] = r1;
                b[2 * p + 1][0] = r2; b[2 * p + 1][1] = r3;
            }
#pragma unroll
            for (int mt = 0; mt < 4; ++mt)
#pragma unroll
                for (int nt = 0; nt < 4; ++nt) MMA16816(acc[mt][nt], a[mt], b[nt]);
        }
    }

    // ---- epilogue: exp(sim - M), row/col partial sums ----
    // frag c layout: c0=(r, 2c4), c1=(r, 2c4+1), c2=(r+8, 2c4), c3=(r+8, 2c4+1)
    // with r = l/4, c4 = l%4 within the m16n8 tile.
    float rp0[4], rp1[4], cq0[4], cq1[4];
#pragma unroll
    for (int i = 0; i < 4; ++i) { rp0[i] = rp1[i] = cq0[i] = cq1[i] = 0.f; }
#pragma unroll
    for (int mt = 0; mt < 4; ++mt)
#pragma unroll
        for (int nt = 0; nt < 4; ++nt) {
            float e0 = __expf(acc[mt][nt][0] - M_SHIFT);
            float e1 = __expf(acc[mt][nt][1] - M_SHIFT);
            float e2 = __expf(acc[mt][nt][2] - M_SHIFT);
            float e3 = __expf(acc[mt][nt][3] - M_SHIFT);
            rp0[mt] += e0 + e1;   // row r
            rp1[mt] += e2 + e3;   // row r+8
            cq0[nt] += e0 + e2;   // col 2c4
            cq1[nt] += e1 + e3;   // col 2c4+1
        }
    // row sums: reduce across the 4 lanes sharing a row (xor 1,2)
#pragma unroll
    for (int o = 1; o <= 2; o <<= 1)
#pragma unroll
        for (int mt = 0; mt < 4; ++mt) {
            rp0[mt] += __shfl_xor_sync(0xffffffffu, rp0[mt], o);
            rp1[mt] += __shfl_xor_sync(0xffffffffu, rp1[mt], o);
        }
    // col sums: reduce across the 8 lane-groups sharing a col (xor 4,8,16)
#pragma unroll
    for (int o = 4; o <= 16; o <<= 1)
#pragma unroll
        for (int nt = 0; nt < 4; ++nt) {
            cq0[nt] += __shfl_xor_sync(0xffffffffu, cq0[nt], o);
            cq1[nt] += __shfl_xor_sync(0xffffffffu, cq1[nt], o);
        }

    float* rowred = (float*)(smem + SMEM_ROWRED);   // [128][4] per warp-col
    float* colred = (float*)(smem + SMEM_COLRED);   // [128][2] per warp-row
    if ((lane & 3) == 0) {
        int rloc = wr * 64 + (lane >> 2);
#pragma unroll
        for (int mt = 0; mt < 4; ++mt) {
            rowred[(rloc + mt * 16) * 4 + wc]     = rp0[mt];
            rowred[(rloc + mt * 16 + 8) * 4 + wc] = rp1[mt];
        }
    }
    if (lane < 4) {
#pragma unroll
        for (int nt = 0; nt < 4; ++nt) {
            int col = wc * 32 + nt * 8 + lane * 2;
            colred[col * 2 + wr]       = cq0[nt];
            colred[(col + 1) * 2 + wr] = cq1[nt];
        }
    }
    __syncthreads();
    if (tid < 128) {
        float rs = rowred[tid * 4] + rowred[tid * 4 + 1] +
                   rowred[tid * 4 + 2] + rowred[tid * 4 + 3];
        g_rowpart[(size_t)blockIdx.x * B_N + rowBase + tid] = rs;
        float cs = colred[tid * 2] + colred[tid * 2 + 1];
        g_colpart[(size_t)blockIdx.y * B_N + colBase + tid] = cs;
    }
}

// ---------------------------------------------------------------------------
// 4a. Per-row loss terms + per-block deterministic tree reduce
// ---------------------------------------------------------------------------
__global__ void finalize1_kernel() {
    int i = blockIdx.x * 256 + threadIdx.x;
    float rs = 0.f, cs = 0.f;
#pragma unroll 4
    for (int t = 0; t < NT; ++t) {
        rs += g_rowpart[(size_t)t * B_N + i];
        cs += g_colpart[(size_t)t * B_N + i];
    }
    float dg = g_diag[i];
    float rw = M_SHIFT + logf(rs) - dg;
    float cw = M_SHIFT + logf(cs) - dg;

    __shared__ float sr[256], sc[256];
    sr[threadIdx.x] = rw;
    sc[threadIdx.x] = cw;
    __syncthreads();
    for (int o = 128; o > 0; o >>= 1) {
        if (threadIdx.x < o) {
            sr[threadIdx.x] += sr[threadIdx.x + o];
            sc[threadIdx.x] += sc[threadIdx.x + o];
        }
        __syncthreads();
    }
    if (threadIdx.x == 0) {
        g_blockRow[blockIdx.x] = sr[0];
        g_blockCol[blockIdx.x] = sc[0];
    }
}

// 4b. Final scalar
__global__ void finalize2_kernel(float* out) {
    float sR = 0.f, sC = 0.f;
    for (int b = 0; b < 64; ++b) { sR += g_blockRow[b]; sC += g_blockCol[b]; }
    out[0] = (sR + sC) / (2.0f * (float)B_N);
}

// ---------------------------------------------------------------------------
extern "C" void kernel_launch(void* const* d_in, const int* in_sizes, int n_in,
                              void* d_out, int out_size) {
    const float* q = (const float*)d_in[0];
    const float* d = (const float*)d_in[1];
    float* out = (float*)d_out;

    cudaFuncSetAttribute(gemm_lse_kernel,
                         cudaFuncAttributeMaxDynamicSharedMemorySize, SMEM_SZ);

    normalize_kernel<<<B_N / 8, 256>>>(q, 1);
    normalize_kernel<<<B_N / 8, 256>>>(d, 0);
    diag_kernel<<<B_N / 8, 256>>>();
    dim3 grid(NT, NT);
    gemm_lse_kernel<<<grid, 256, SMEM_SZ>>>();
    finalize1_kernel<<<B_N / 256, 256>>>();
    finalize2_kernel<<<1, 1>>>(out);
}

// round 10
// speedup vs baseline: 7.4717x; 1.0741x over previous
#include <cuda_runtime.h>
#include <cuda_bf16.h>
#include <math.h>
#include <cstdint>

// InfoNCE loss. B=16384, D=256, T=0.07. bf16 mma.sync path (compute_103-safe).
// Persistent row-tile CTAs: A(q) tile loaded once, B(d) tiles streamed with
// cp.async double buffering; row partials accumulate in registers across all
// col tiles. exp(sim - M), M = 1/T >= max sim -> stable fixed-shift LSE,
// no atomics, fully deterministic. sim (1 GB) never materialized.

#define B_N 16384
#define D_K 256
#define NT  128
#define M_SHIFT 14.285714285714286f   // 1/0.07

static __device__ __nv_bfloat16 g_qb[B_N * D_K];
static __device__ __nv_bfloat16 g_db[B_N * D_K];
static __device__ float g_diag[B_N];
static __device__ float g_rowsum[B_N];         // sum over all col tiles
static __device__ float g_colpart[NT * B_N];   // [rowTile][col]
static __device__ float g_blockRow[64];
static __device__ float g_blockCol[64];

// ---------------- PTX helpers (plain sm_103-safe) --------------------------
__device__ __forceinline__ uint32_t smem_u32(const void* p) {
    uint32_t a;
    asm("{ .reg .u64 t; cvta.to.shared.u64 t, %1; cvt.u32.u64 %0, t; }" : "=r"(a) : "l"(p));
    return a;
}
__device__ __forceinline__ void cp16(uint32_t dst, const void* src) {
    asm volatile("cp.async.cg.shared.global [%0], [%1], 16;" :: "r"(dst), "l"(src) : "memory");
}
#define CP_COMMIT() asm volatile("cp.async.commit_group;" ::: "memory")
#define CP_WAIT(n)  asm volatile("cp.async.wait_group %0;" :: "n"(n) : "memory")

#define LDSM4(r0, r1, r2, r3, addr)                                          \
    asm volatile("ldmatrix.sync.aligned.m8n8.x4.shared.b16 {%0,%1,%2,%3}, [%4];" \
        : "=r"(r0), "=r"(r1), "=r"(r2), "=r"(r3) : "r"(addr))

#define MMA16816(c, a, b)                                                    \
    asm volatile("mma.sync.aligned.m16n8k16.row.col.f32.bf16.bf16.f32 "      \
        "{%0,%1,%2,%3}, {%4,%5,%6,%7}, {%8,%9}, {%0,%1,%2,%3};"              \
        : "+f"((c)[0]), "+f"((c)[1]), "+f"((c)[2]), "+f"((c)[3])             \
        : "r"((a)[0]), "r"((a)[1]), "r"((a)[2]), "r"((a)[3]),                \
          "r"((b)[0]), "r"((b)[1]))

// ---------------------------------------------------------------------------
// 1. Normalize -> bf16 (q scaled by 1/T). One warp per row.
// ---------------------------------------------------------------------------
__global__ void normalize_kernel(const float* __restrict__ in, int is_q) {
    int warp = threadIdx.x >> 5;
    int lane = threadIdx.x & 31;
    int row  = blockIdx.x * 8 + warp;
    const float* src = in + (size_t)row * D_K;
    float v[8];
    float s = 0.f;
#pragma unroll
    for (int j = 0; j < 8; ++j) { v[j] = src[j * 32 + lane]; s += v[j] * v[j]; }
#pragma unroll
    for (int o = 16; o > 0; o >>= 1) s += __shfl_xor_sync(0xffffffffu, s, o);
    float extra = is_q ? (1.0f / 0.07f) : 1.0f;
    float scale = extra / fmaxf(sqrtf(s), 1e-12f);
    __nv_bfloat16* dst = (is_q ? g_qb : g_db) + (size_t)row * D_K;
#pragma unroll
    for (int j = 0; j < 8; ++j) dst[j * 32 + lane] = __float2bfloat16(v[j] * scale);
}

// ---------------------------------------------------------------------------
// 2. diag[i] = qb_i . db_i  (fp32 accumulate; matches bf16 GEMM inputs)
// ---------------------------------------------------------------------------
__global__ void diag_kernel() {
    int warp = threadIdx.x >> 5;
    int lane = threadIdx.x & 31;
    int row  = blockIdx.x * 8 + warp;
    const __nv_bfloat16* a = g_qb + (size_t)row * D_K;
    const __nv_bfloat16* b = g_db + (size_t)row * D_K;
    float s = 0.f;
#pragma unroll
    for (int j = 0; j < 8; ++j) {
        int c = j * 32 + lane;
        s += __bfloat162float(a[c]) * __bfloat162float(b[c]);
    }
#pragma unroll
    for (int o = 16; o > 0; o >>= 1) s += __shfl_xor_sync(0xffffffffu, s, o);
    if (lane == 0) g_diag[row] = s;
}

// ---------------------------------------------------------------------------
// 3. Persistent GEMM + exp partials. Grid 128 (row tiles), 256 threads.
//    SMEM: A 64K @0, B buf0 64K @65536, B buf1 64K @131072,
//          colred 1K @196608, rowred 2K @197632.
//    Tile layout: [row][16B chunk c], 32 chunks/row, swizzle c ^= (row & 7).
// ---------------------------------------------------------------------------
#define SMEM_B0     65536
#define SMEM_B1     131072
#define SMEM_COLRED 196608
#define SMEM_ROWRED 197632
#define SMEM_SZ     199680

__device__ __forceinline__ void load_tile(uint32_t dstBase,
                                          const __nv_bfloat16* src, int tid) {
#pragma unroll
    for (int it = 0; it < 16; ++it) {
        int e = it * 256 + tid;          // 0..4095
        int r = e >> 5, c = e & 31;      // row, 16B chunk (full K=256)
        cp16(dstBase + r * 512 + ((c ^ (r & 7)) << 4),
             (const char*)(src + (size_t)r * D_K) + c * 16);
    }
}

__global__ __launch_bounds__(256, 1) void gemm_lse_kernel() {
    extern __shared__ char smem[];
    uint32_t sb = smem_u32(smem);
    int tid = threadIdx.x;
    int lane = tid & 31;
    int wid  = tid >> 5;
    int wr = wid >> 2;         // warp row (0..1) -> 64 rows
    int wc = wid & 3;          // warp col (0..3) -> 32 cols
    int rowBase = blockIdx.x * 128;

    // A (q rows) once; B tile 0 prefetch.
    load_tile(sb, g_qb + (size_t)rowBase * D_K, tid);
    CP_COMMIT();
    load_tile(sb + SMEM_B0, g_db, tid);
    CP_COMMIT();

    // per-lane ldmatrix row/chunk components
    int aRowL   = wr * 64 + (lane & 15);                          // + mt*16
    int aChunkL = lane >> 4;                                      // + 2*ks
    int bRowL   = wc * 32 + ((lane >> 4) & 1) * 8 + (lane & 7);   // + p*16
    int bChunkL = (lane >> 3) & 1;                                // + 2*ks

    // row partials accumulate across ALL col tiles (registers)
    float rp0[4], rp1[4];
#pragma unroll
    for (int i = 0; i < 4; ++i) { rp0[i] = rp1[i] = 0.f; }

    float* colred = (float*)(smem + SMEM_COLRED);

#pragma unroll 1
    for (int t = 0; t < NT; ++t) {
        if (t + 1 < NT) {
            load_tile(sb + (((t + 1) & 1) ? SMEM_B1 : SMEM_B0),
                      g_db + (size_t)(t + 1) * 128 * D_K, tid);
            CP_COMMIT();
            CP_WAIT(1);
        } else {
            CP_WAIT(0);
        }
        __syncthreads();

        float acc[4][4][4];
#pragma unroll
        for (int mt = 0; mt < 4; ++mt)
#pragma unroll
            for (int nt = 0; nt < 4; ++nt)
#pragma unroll
                for (int k = 0; k < 4; ++k) acc[mt][nt][k] = 0.f;

        uint32_t bBase = sb + ((t & 1) ? SMEM_B1 : SMEM_B0);
#pragma unroll
        for (int ks = 0; ks < 16; ++ks) {
            uint32_t a[4][4];
#pragma unroll
            for (int mt = 0; mt < 4; ++mt) {
                int rrow = aRowL + mt * 16;
                int cc = 2 * ks + aChunkL;
                uint32_t ad = sb + rrow * 512 + ((cc ^ (rrow & 7)) << 4);
                LDSM4(a[mt][0], a[mt][1], a[mt][2], a[mt][3], ad);
            }
            uint32_t b[4][2];
#pragma unroll
            for (int p = 0; p < 2; ++p) {
                int rrow = bRowL + p * 16;
                int cc = 2 * ks + bChunkL;
                uint32_t bd = bBase + rrow * 512 + ((cc ^ (rrow & 7)) << 4);
                uint32_t r0, r1, r2, r3;
                LDSM4(r0, r1, r2, r3, bd);
                b[2 * p][0] = r0; b[2 * p][1] = r1;
                b[2 * p + 1][0] = r2; b[2 * p + 1][1] = r3;
            }
#pragma unroll
            for (int mt = 0; mt < 4; ++mt)
#pragma unroll
                for (int nt = 0; nt < 4; ++nt) MMA16816(acc[mt][nt], a[mt], b[nt]);
        }

        // ---- epilogue: exp(sim - M); rows -> registers, cols -> smem ----
        float cq0[4], cq1[4];
#pragma unroll
        for (int i = 0; i < 4; ++i) { cq0[i] = cq1[i] = 0.f; }
#pragma unroll
        for (int mt = 0; mt < 4; ++mt)
#pragma unroll
            for (int nt = 0; nt < 4; ++nt) {
                float e0 = __expf(acc[mt][nt][0] - M_SHIFT);
                float e1 = __expf(acc[mt][nt][1] - M_SHIFT);
                float e2 = __expf(acc[mt][nt][2] - M_SHIFT);
                float e3 = __expf(acc[mt][nt][3] - M_SHIFT);
                rp0[mt] += e0 + e1;
                rp1[mt] += e2 + e3;
                cq0[nt] += e0 + e2;
                cq1[nt] += e1 + e3;
            }
        // col sums: reduce across the 8 lane-groups sharing a col
#pragma unroll
        for (int o = 4; o <= 16; o <<= 1)
#pragma unroll
            for (int nt = 0; nt < 4; ++nt) {
                cq0[nt] += __shfl_xor_sync(0xffffffffu, cq0[nt], o);
                cq1[nt] += __shfl_xor_sync(0xffffffffu, cq1[nt], o);
            }
        if (lane < 4) {
#pragma unroll
            for (int nt = 0; nt < 4; ++nt) {
                int col = wc * 32 + nt * 8 + lane * 2;
                colred[col * 2 + wr]       = cq0[nt];
                colred[(col + 1) * 2 + wr] = cq1[nt];
            }
        }
        __syncthreads();
        if (tid < 128) {
            float cs = colred[tid * 2] + colred[tid * 2 + 1];
            g_colpart[(size_t)blockIdx.x * B_N + t * 128 + tid] = cs;
        }
    }

    // ---- final row sums (once per CTA) ----
#pragma unroll
    for (int o = 1; o <= 2; o <<= 1)
#pragma unroll
        for (int mt = 0; mt < 4; ++mt) {
            rp0[mt] += __shfl_xor_sync(0xffffffffu, rp0[mt], o);
            rp1[mt] += __shfl_xor_sync(0xffffffffu, rp1[mt], o);
        }
    float* rowred = (float*)(smem + SMEM_ROWRED);
    __syncthreads();
    if ((lane & 3) == 0) {
        int rloc = wr * 64 + (lane >> 2);
#pragma unroll
        for (int mt = 0; mt < 4; ++mt) {
            rowred[(rloc + mt * 16) * 4 + wc]     = rp0[mt];
            rowred[(rloc + mt * 16 + 8) * 4 + wc] = rp1[mt];
        }
    }
    __syncthreads();
    if (tid < 128) {
        float rs = rowred[tid * 4] + rowred[tid * 4 + 1] +
                   rowred[tid * 4 + 2] + rowred[tid * 4 + 3];
        g_rowsum[rowBase + tid] = rs;
    }
}

// ---------------------------------------------------------------------------
// 4a. Per-row loss terms + per-block deterministic tree reduce
// ---------------------------------------------------------------------------
__global__ void finalize1_kernel() {
    int i = blockIdx.x * 256 + threadIdx.x;
    float cs = 0.f;
#pragma unroll 4
    for (int t = 0; t < NT; ++t) cs += g_colpart[(size_t)t * B_N + i];
    float rs = g_rowsum[i];
    float dg = g_diag[i];
    float rw = M_SHIFT + logf(rs) - dg;
    float cw = M_SHIFT + logf(cs) - dg;

    __shared__ float sr[256], sc[256];
    sr[threadIdx.x] = rw;
    sc[threadIdx.x] = cw;
    __syncthreads();
    for (int o = 128; o > 0; o >>= 1) {
        if (threadIdx.x < o) {
            sr[threadIdx.x] += sr[threadIdx.x + o];
            sc[threadIdx.x] += sc[threadIdx.x + o];
        }
        __syncthreads();
    }
    if (threadIdx.x == 0) {
        g_blockRow[blockIdx.x] = sr[0];
        g_blockCol[blockIdx.x] = sc[0];
    }
}

// 4b. Final scalar
__global__ void finalize2_kernel(float* out) {
    float sR = 0.f, sC = 0.f;
    for (int b = 0; b < 64; ++b) { sR += g_blockRow[b]; sC += g_blockCol[b]; }
    out[0] = (sR + sC) / (2.0f * (float)B_N);
}

// ---------------------------------------------------------------------------
extern "C" void kernel_launch(void* const* d_in, const int* in_sizes, int n_in,
                              void* d_out, int out_size) {
    const float* q = (const float*)d_in[0];
    const float* d = (const float*)d_in[1];
    float* out = (float*)d_out;

    cudaFuncSetAttribute(gemm_lse_kernel,
                         cudaFuncAttributeMaxDynamicSharedMemorySize, SMEM_SZ);

    normalize_kernel<<<B_N / 8, 256>>>(q, 1);
    normalize_kernel<<<B_N / 8, 256>>>(d, 0);
    diag_kernel<<<B_N / 8, 256>>>();
    gemm_lse_kernel<<<NT, 256, SMEM_SZ>>>();
    finalize1_kernel<<<B_N / 256, 256>>>();
    finalize2_kernel<<<1, 1>>>(out);
}